// round 5
// baseline (speedup 1.0000x reference)
#include <cuda_runtime.h>
#include <math.h>

#define B_ 32
#define T_ 64
#define N_ 32
#define D_ 128
#define E_ 8
#define K_ 2
#define XT 68    // [feature][time] stride: 64 + 4 pad (16B-aligned rows for LDS.128)
#define AT 132   // att_t [kt][row] stride: 128 + 4 pad (16B-aligned)

typedef unsigned long long u64;

__device__ int   d_eidx[B_][K_];
__device__ float d_gateg[B_][K_];

// ---- f32x2 packed-math helpers ----
__device__ __forceinline__ u64 f2fma(u64 a, u64 b, u64 c) {
    u64 d; asm("fma.rn.f32x2 %0, %1, %2, %3;" : "=l"(d) : "l"(a), "l"(b), "l"(c)); return d;
}
__device__ __forceinline__ u64 f2mul(u64 a, u64 b) {
    u64 d; asm("mul.rn.f32x2 %0, %1, %2;" : "=l"(d) : "l"(a), "l"(b)); return d;
}
__device__ __forceinline__ u64 fpack(float lo, float hi) {
    u64 d; asm("mov.b64 %0, {%1, %2};" : "=l"(d) : "f"(lo), "f"(hi)); return d;
}
__device__ __forceinline__ u64 fdup(float v) { return fpack(v, v); }
__device__ __forceinline__ float2 funpack(u64 v) {
    float2 r; asm("mov.b64 {%0, %1}, %2;" : "=f"(r.x), "=f"(r.y) : "l"(v)); return r;
}

// ---------------------------------------------------------------------------
// Kernel 1: gating (eval mode)
// ---------------------------------------------------------------------------
__global__ void gate_kernel(const float* __restrict__ x,
                            const float* __restrict__ Wg) {
    const int b   = blockIdx.x;
    const int tid = threadIdx.x;  // 128 threads
    __shared__ float smean[D_];
    __shared__ float slog[E_];

    const float* xb = x + (size_t)b * T_ * N_ * D_;
    float s = 0.f;
    for (int i = 0; i < T_ * N_; ++i) s += xb[(size_t)i * D_ + tid];
    smean[tid] = s * (1.0f / (float)(T_ * N_));
    __syncthreads();

    if (tid < E_) {
        float l = 0.f;
        for (int d = 0; d < D_; ++d) l += smean[d] * Wg[d * E_ + tid];
        slog[tid] = l;
    }
    __syncthreads();

    if (tid == 0) {
        int i0 = 0; float v0 = slog[0];
        for (int e = 1; e < E_; ++e) if (slog[e] > v0) { v0 = slog[e]; i0 = e; }
        int i1 = -1; float v1 = -3.0e38f;
        for (int e = 0; e < E_; ++e) if (e != i0 && slog[e] > v1) { v1 = slog[e]; i1 = e; }
        const float e1  = expf(v1 - v0);
        const float inv = 1.0f / (1.0f + e1);
        d_eidx[b][0]  = i0; d_eidx[b][1]  = i1;
        d_gateg[b][0] = inv; d_gateg[b][1] = e1 * inv;
    }
}

// ---------------------------------------------------------------------------
// Kernel 2: one CTA per (b, n). 512 threads, 4x4 register tiles, LDS.128.
// SMEM: xs_t[128][68] | kst[128][68] (k_t then o_t) | vs[64][128] |
//       ar (att_t[64][132] then o1_t[128][68]) -> 34304 floats = 134 KB
// ---------------------------------------------------------------------------
__global__ __launch_bounds__(512, 1)
void moe_kernel(const float* __restrict__ x,
                const float* __restrict__ Wd,
                const float* __restrict__ bd,
                const float* __restrict__ Ws,
                const float* __restrict__ bs,
                float* __restrict__ out) {
    extern __shared__ float sm[];
    float* xs  = sm;             // 8704 floats  [d][t] stride 68
    float* kst = sm + 8704;      // 8704 floats  [feat][t] stride 68
    float* vs  = sm + 17408;     // 8192 floats  [t][feat]
    float* ar  = sm + 25600;     // 8704 floats  att_t[kt][row] (132) / o1_t (68)

    const int n    = blockIdx.x;
    const int b    = blockIdx.y;
    const int tid  = threadIdx.x;
    const int lane = tid & 31;
    const int wid  = tid >> 5;

    // ---- load x slab [T][D] coalesced, store transposed xs_t[d][t] ----
    {
        const float4* xg = (const float4*)(x + ((size_t)b * T_ * N_ + n) * D_);
        #pragma unroll
        for (int i = tid; i < T_ * D_ / 4; i += 512) {
            const int t  = i >> 5;
            const int c4 = i & 31;
            float4 v = xg[(size_t)t * (N_ * D_ / 4) + c4];
            const int d0 = c4 * 4;
            xs[(d0 + 0) * XT + t] = v.x;
            xs[(d0 + 1) * XT + t] = v.y;
            xs[(d0 + 2) * XT + t] = v.z;
            xs[(d0 + 3) * XT + t] = v.w;
        }
    }

    // weight-GEMM mapping: cg (col quad, lane) × rg (row quad, warp-uniform)
    const int cg = tid & 31;
    const int rg = tid >> 5;        // 0..15
    const int c0 = cg * 4;
    const int t0 = rg * 4;

    float accv[4][4];   // [col][row]
    #pragma unroll
    for (int c = 0; c < 4; ++c)
        #pragma unroll
        for (int r = 0; r < 4; ++r) accv[c][r] = 0.f;

    __syncthreads();

    for (int slot = 0; slot < K_; ++slot) {
        const int   e = d_eidx[b][slot];
        const float g = d_gateg[b][slot];
        const float* W0 = Wd + ((size_t)(e * 2 + 0) * N_ + n) * D_ * D_;
        const float* W1 = Wd + ((size_t)(e * 2 + 1) * N_ + n) * D_ * D_;
        const float* b0 = bd + ((size_t)(e * 2 + 0) * N_ + n) * D_;
        const float* b1 = bd + ((size_t)(e * 2 + 1) * N_ + n) * D_;

        // ---- GEMM1: k = x@W0+b0 (transposed store), v = x@W1+b1 ----
        {
            u64 aK[4][2], aV[4][2];
            const float4 bk = *(const float4*)&b0[c0];
            const float4 bv = *(const float4*)&b1[c0];
            aK[0][0] = aK[0][1] = fdup(bk.x);
            aK[1][0] = aK[1][1] = fdup(bk.y);
            aK[2][0] = aK[2][1] = fdup(bk.z);
            aK[3][0] = aK[3][1] = fdup(bk.w);
            aV[0][0] = aV[0][1] = fdup(bv.x);
            aV[1][0] = aV[1][1] = fdup(bv.y);
            aV[2][0] = aV[2][1] = fdup(bv.z);
            aV[3][0] = aV[3][1] = fdup(bv.w);

            #pragma unroll 4
            for (int d = 0; d < D_; ++d) {
                const ulonglong2 xv = *(const ulonglong2*)&xs[d * XT + t0];
                const float4 w0 = *(const float4*)&W0[d * D_ + c0];
                const float4 w1 = *(const float4*)&W1[d * D_ + c0];
                const u64 w00 = fdup(w0.x), w01 = fdup(w0.y), w02 = fdup(w0.z), w03 = fdup(w0.w);
                const u64 w10 = fdup(w1.x), w11 = fdup(w1.y), w12 = fdup(w1.z), w13 = fdup(w1.w);
                aK[0][0] = f2fma(xv.x, w00, aK[0][0]); aK[0][1] = f2fma(xv.y, w00, aK[0][1]);
                aK[1][0] = f2fma(xv.x, w01, aK[1][0]); aK[1][1] = f2fma(xv.y, w01, aK[1][1]);
                aK[2][0] = f2fma(xv.x, w02, aK[2][0]); aK[2][1] = f2fma(xv.y, w02, aK[2][1]);
                aK[3][0] = f2fma(xv.x, w03, aK[3][0]); aK[3][1] = f2fma(xv.y, w03, aK[3][1]);
                aV[0][0] = f2fma(xv.x, w10, aV[0][0]); aV[0][1] = f2fma(xv.y, w10, aV[0][1]);
                aV[1][0] = f2fma(xv.x, w11, aV[1][0]); aV[1][1] = f2fma(xv.y, w11, aV[1][1]);
                aV[2][0] = f2fma(xv.x, w12, aV[2][0]); aV[2][1] = f2fma(xv.y, w12, aV[2][1]);
                aV[3][0] = f2fma(xv.x, w13, aV[3][0]); aV[3][1] = f2fma(xv.y, w13, aV[3][1]);
            }
            // k: transposed store, one STS.128 per column
            #pragma unroll
            for (int c = 0; c < 4; ++c) {
                ulonglong2 kk; kk.x = aK[c][0]; kk.y = aK[c][1];
                *(ulonglong2*)&kst[(c0 + c) * XT + t0] = kk;
            }
            // v: row-major store, one STS.128 per row
            #pragma unroll
            for (int p = 0; p < 2; ++p) {
                const float2 q0 = funpack(aV[0][p]);
                const float2 q1 = funpack(aV[1][p]);
                const float2 q2 = funpack(aV[2][p]);
                const float2 q3 = funpack(aV[3][p]);
                float4 r0; r0.x = q0.x; r0.y = q1.x; r0.z = q2.x; r0.w = q3.x;
                float4 r1; r1.x = q0.y; r1.y = q1.y; r1.z = q2.y; r1.w = q3.y;
                *(float4*)&vs[(t0 + 2 * p)     * D_ + c0] = r0;
                *(float4*)&vs[(t0 + 2 * p + 1) * D_ + c0] = r1;
            }
        }
        __syncthreads();

        // ---- attention scores: att_t[kt][hh*64+qt] = (q.k)/8, 4kt x 4q tile ----
        {
            const int ktg = tid & 15;
            const int qg  = (tid >> 4) & 15;
            const int hh  = tid >> 8;
            const int kt0 = ktg * 4;
            const int q0  = qg * 4;
            const int db  = hh * 64;

            u64 acc[4][2];
            #pragma unroll
            for (int c = 0; c < 4; ++c) { acc[c][0] = 0ull; acc[c][1] = 0ull; }

            #pragma unroll 4
            for (int d = 0; d < 64; ++d) {
                const ulonglong2 xq = *(const ulonglong2*)&xs[(db + d) * XT + q0];
                const float4 kk = *(const float4*)&kst[(db + d) * XT + kt0];
                const u64 k0 = fdup(kk.x), k1 = fdup(kk.y), k2 = fdup(kk.z), k3 = fdup(kk.w);
                acc[0][0] = f2fma(xq.x, k0, acc[0][0]); acc[0][1] = f2fma(xq.y, k0, acc[0][1]);
                acc[1][0] = f2fma(xq.x, k1, acc[1][0]); acc[1][1] = f2fma(xq.y, k1, acc[1][1]);
                acc[2][0] = f2fma(xq.x, k2, acc[2][0]); acc[2][1] = f2fma(xq.y, k2, acc[2][1]);
                acc[3][0] = f2fma(xq.x, k3, acc[3][0]); acc[3][1] = f2fma(xq.y, k3, acc[3][1]);
            }
            const u64 sc = fdup(0.125f);
            #pragma unroll
            for (int c = 0; c < 4; ++c) {
                ulonglong2 st; st.x = f2mul(acc[c][0], sc); st.y = f2mul(acc[c][1], sc);
                *(ulonglong2*)&ar[(kt0 + c) * AT + db + q0] = st;
            }
        }
        __syncthreads();

        // ---- softmax over kt: 16 warps × 8 rows ----
        for (int r = wid * 8; r < wid * 8 + 8; ++r) {
            const float a0 = ar[lane * AT + r];
            const float a1 = ar[(lane + 32) * AT + r];
            float m = fmaxf(a0, a1);
            #pragma unroll
            for (int o = 16; o > 0; o >>= 1) m = fmaxf(m, __shfl_xor_sync(0xffffffffu, m, o));
            const float e0 = __expf(a0 - m);
            const float e1x = __expf(a1 - m);
            float s = e0 + e1x;
            #pragma unroll
            for (int o = 16; o > 0; o >>= 1) s += __shfl_xor_sync(0xffffffffu, s, o);
            const float inv = 1.0f / s;
            ar[lane * AT + r]        = e0 * inv;
            ar[(lane + 32) * AT + r] = e1x * inv;
        }
        __syncthreads();

        // ---- oGEMM: o_t[dc][t] = sum_kt att_t[kt][hh*64+t] * v[kt][dc], 4dc x 4t ----
        {
            const int dcg = tid & 31;
            const int tg  = tid >> 5;
            const int dc0 = dcg * 4;
            const int tq  = tg * 4;
            const int hh  = dcg >> 4;
            const int rb  = hh * 64 + tq;

            u64 acc[4][2];
            #pragma unroll
            for (int c = 0; c < 4; ++c) { acc[c][0] = 0ull; acc[c][1] = 0ull; }

            #pragma unroll 4
            for (int kt = 0; kt < 64; ++kt) {
                const ulonglong2 at2 = *(const ulonglong2*)&ar[kt * AT + rb];
                const float4 vv = *(const float4*)&vs[kt * D_ + dc0];
                const u64 v0 = fdup(vv.x), v1 = fdup(vv.y), v2 = fdup(vv.z), v3 = fdup(vv.w);
                acc[0][0] = f2fma(at2.x, v0, acc[0][0]); acc[0][1] = f2fma(at2.y, v0, acc[0][1]);
                acc[1][0] = f2fma(at2.x, v1, acc[1][0]); acc[1][1] = f2fma(at2.y, v1, acc[1][1]);
                acc[2][0] = f2fma(at2.x, v2, acc[2][0]); acc[2][1] = f2fma(at2.y, v2, acc[2][1]);
                acc[3][0] = f2fma(at2.x, v3, acc[3][0]); acc[3][1] = f2fma(at2.y, v3, acc[3][1]);
            }
            #pragma unroll
            for (int c = 0; c < 4; ++c) {
                ulonglong2 st; st.x = acc[c][0]; st.y = acc[c][1];
                *(ulonglong2*)&kst[(dc0 + c) * XT + tq] = st;
            }
        }
        __syncthreads();

        const float* Wsh0 = Ws + (size_t)(e * 2 + 0) * D_ * D_;
        const float* Wsh1 = Ws + (size_t)(e * 2 + 1) * D_ * D_;
        const float* bsh0 = bs + (e * 2 + 0) * D_;
        const float* bsh1 = bs + (e * 2 + 1) * D_;

        // ---- GEMM2: o1 = relu(o @ Ws0 + bs0) -> ar as o1_t ----
        {
            u64 a2[4][2];
            const float4 bb = *(const float4*)&bsh0[c0];
            a2[0][0] = a2[0][1] = fdup(bb.x);
            a2[1][0] = a2[1][1] = fdup(bb.y);
            a2[2][0] = a2[2][1] = fdup(bb.z);
            a2[3][0] = a2[3][1] = fdup(bb.w);
            #pragma unroll 4
            for (int d = 0; d < D_; ++d) {
                const ulonglong2 ov = *(const ulonglong2*)&kst[d * XT + t0];
                const float4 w = *(const float4*)&Wsh0[d * D_ + c0];
                const u64 w0 = fdup(w.x), w1 = fdup(w.y), w2 = fdup(w.z), w3 = fdup(w.w);
                a2[0][0] = f2fma(ov.x, w0, a2[0][0]); a2[0][1] = f2fma(ov.y, w0, a2[0][1]);
                a2[1][0] = f2fma(ov.x, w1, a2[1][0]); a2[1][1] = f2fma(ov.y, w1, a2[1][1]);
                a2[2][0] = f2fma(ov.x, w2, a2[2][0]); a2[2][1] = f2fma(ov.y, w2, a2[2][1]);
                a2[3][0] = f2fma(ov.x, w3, a2[3][0]); a2[3][1] = f2fma(ov.y, w3, a2[3][1]);
            }
            #pragma unroll
            for (int c = 0; c < 4; ++c) {
                const float2 u0 = funpack(a2[c][0]);
                const float2 u1 = funpack(a2[c][1]);
                ulonglong2 st;
                st.x = fpack(fmaxf(u0.x, 0.f), fmaxf(u0.y, 0.f));
                st.y = fpack(fmaxf(u1.x, 0.f), fmaxf(u1.y, 0.f));
                *(ulonglong2*)&ar[(c0 + c) * XT + t0] = st;
            }
        }
        __syncthreads();

        // ---- GEMM3: out_e = o1 @ Ws1 + bs1 ; accv += g * exp(out_e) ----
        {
            u64 a3[4][2];
            const float4 bb = *(const float4*)&bsh1[c0];
            a3[0][0] = a3[0][1] = fdup(bb.x);
            a3[1][0] = a3[1][1] = fdup(bb.y);
            a3[2][0] = a3[2][1] = fdup(bb.z);
            a3[3][0] = a3[3][1] = fdup(bb.w);
            #pragma unroll 4
            for (int d = 0; d < D_; ++d) {
                const ulonglong2 ov = *(const ulonglong2*)&ar[d * XT + t0];
                const float4 w = *(const float4*)&Wsh1[d * D_ + c0];
                const u64 w0 = fdup(w.x), w1 = fdup(w.y), w2 = fdup(w.z), w3 = fdup(w.w);
                a3[0][0] = f2fma(ov.x, w0, a3[0][0]); a3[0][1] = f2fma(ov.y, w0, a3[0][1]);
                a3[1][0] = f2fma(ov.x, w1, a3[1][0]); a3[1][1] = f2fma(ov.y, w1, a3[1][1]);
                a3[2][0] = f2fma(ov.x, w2, a3[2][0]); a3[2][1] = f2fma(ov.y, w2, a3[2][1]);
                a3[3][0] = f2fma(ov.x, w3, a3[3][0]); a3[3][1] = f2fma(ov.y, w3, a3[3][1]);
            }
            #pragma unroll
            for (int c = 0; c < 4; ++c) {
                const float2 u0 = funpack(a3[c][0]);
                const float2 u1 = funpack(a3[c][1]);
                accv[c][0] += g * __expf(u0.x);
                accv[c][1] += g * __expf(u0.y);
                accv[c][2] += g * __expf(u1.x);
                accv[c][3] += g * __expf(u1.y);
            }
        }
        __syncthreads();
    }

    // ---- combine epilogue: log(sum g*exp), EPS guard; STG.128 per row ----
    const float EPSF = 2.2204460492503131e-16f;
    #pragma unroll
    for (int r = 0; r < 4; ++r) {
        float v0 = accv[0][r]; if (v0 == 0.f) v0 = EPSF;
        float v1 = accv[1][r]; if (v1 == 0.f) v1 = EPSF;
        float v2 = accv[2][r]; if (v2 == 0.f) v2 = EPSF;
        float v3 = accv[3][r]; if (v3 == 0.f) v3 = EPSF;
        float4 o4;
        o4.x = __logf(v0); o4.y = __logf(v1); o4.z = __logf(v2); o4.w = __logf(v3);
        *(float4*)&out[(((size_t)b * T_ + t0 + r) * N_ + n) * D_ + c0] = o4;
    }
}

// ---------------------------------------------------------------------------
// launcher
// ---------------------------------------------------------------------------
extern "C" void kernel_launch(void* const* d_in, const int* in_sizes, int n_in,
                              void* d_out, int out_size) {
    const float* x  = (const float*)d_in[0];
    const float* Wg = (const float*)d_in[1];
    const float* Wd = (const float*)d_in[2];
    const float* bd = (const float*)d_in[3];
    const float* Ws = (const float*)d_in[4];
    const float* bs = (const float*)d_in[5];
    float* out = (float*)d_out;

    const int smem_bytes = 34304 * (int)sizeof(float); // 137216 B
    cudaFuncSetAttribute(moe_kernel, cudaFuncAttributeMaxDynamicSharedMemorySize, smem_bytes);

    gate_kernel<<<B_, 128>>>(x, Wg);
    dim3 grid(N_, B_);
    moe_kernel<<<grid, 512, smem_bytes>>>(x, Wd, bd, Ws, bs, out);
}